// round 6
// baseline (speedup 1.0000x reference)
#include <cuda_runtime.h>
#include <math.h>

// Problem constants (fixed by the bench problem)
#define AA     48          // atoms per batch
#define SS     4           // num species
#define NR     16          // num radial shifts (ShfR)
#define NAA    4           // num angular radial shifts (ShfA)
#define NZ     8           // num angular shifts (ShfZ)
#define NPAIRS (SS*(SS+1)/2)   // 10
#define RADD   (SS*NR)         // 64
#define ANGD   (NPAIRS*NAA*NZ) // 320
#define OUTD   (RADD+ANGD)     // 384
#define RCR    5.2f
#define RCA    3.5f
#define PI_F   3.14159265358979323846f

__global__ __launch_bounds__(256) void aev_kernel(
    const int*   __restrict__ species,   // [B, A]
    const float* __restrict__ coords,    // [B, A, 3]
    const float* __restrict__ EtaR,      // [1]
    const float* __restrict__ ShfR,      // [NR]
    const float* __restrict__ EtaA,      // [1]
    const float* __restrict__ Zeta,      // [1]
    const float* __restrict__ ShfA,      // [NAA]
    const float* __restrict__ ShfZ,      // [NZ]
    float*       __restrict__ out)       // [B, A, OUTD]
{
    __shared__ float cxyz[AA*3];
    __shared__ int   sp[AA];
    __shared__ int   cntR, cntA;
    // radial compacted
    __shared__ float rd[AA], rf[AA];
    __shared__ int   rs[AA];
    __shared__ float accR[RADD];
    __shared__ float shfR_s[NR];
    // angular compacted (indexed by slot)
    __shared__ float adx[AA], ady[AA], adz[AA], ad[AA], afc[AA];
    __shared__ int   spA[AA];
    __shared__ float accA[ANGD];
    __shared__ float shfA_s[NAA], czZ[NZ], szZ[NZ];
    __shared__ float etaR_sh, etaA_sh, zeta_sh;

    const int tid  = threadIdx.x;
    const int wid  = tid >> 5;
    const int lane = tid & 31;
    const int aidx = blockIdx.x;       // global atom index
    const int i    = aidx % AA;
    const int b    = aidx / AA;

    // ---------------- prologue (all 256 threads) ----------------
    if (tid == 0) {
        cntR = 0; cntA = 0;
        etaR_sh = EtaR[0]; etaA_sh = EtaA[0]; zeta_sh = Zeta[0];
    }
    if (tid < 36) ((float4*)cxyz)[tid] = ((const float4*)(coords + (size_t)b*AA*3))[tid];
    if (tid < AA) sp[tid] = species[b*AA + tid];
    if (tid < NR) shfR_s[tid] = ShfR[tid];
    if (tid < NAA) shfA_s[tid] = ShfA[tid];
    if (tid < NZ) { float s = ShfZ[tid]; czZ[tid] = __cosf(s); szZ[tid] = __sinf(s); }
    if (tid < RADD) accR[tid] = 0.0f;
    for (int t = tid; t < ANGD; t += 256) accA[t] = 0.0f;
    __syncthreads();

    const bool  validI = (sp[i] >= 0);
    const float xi = cxyz[3*i], yi = cxyz[3*i+1], zi = cxyz[3*i+2];

    if (tid < AA) {
        int j = tid;
        float dx = xi - cxyz[3*j], dy = yi - cxyz[3*j+1], dz = zi - cxyz[3*j+2];
        float d  = sqrtf(dx*dx + dy*dy + dz*dz);
        bool pv = validI && (sp[j] >= 0) && (j != i);
        if (pv && d <= RCR) {
            int s = atomicAdd(&cntR, 1);
            rd[s] = d;
            rf[s] = 0.5f*__cosf(PI_F * d * (1.0f/RCR)) + 0.5f;
            rs[s] = sp[j];
        }
        if (pv && d <= RCA) {
            int s = atomicAdd(&cntA, 1);
            adx[s] = dx; ady[s] = dy; adz[s] = dz; ad[s] = d;
            afc[s] = 0.5f*__cosf(PI_F * d * (1.0f/RCA)) + 0.5f;
            spA[s] = sp[j];
        }
    }
    __syncthreads();

    if (tid < 128) {
        // ================= RADIAL (warps 0-3): accR[0..64) =================
        const int   Mr   = cntR;
        const float etaR = etaR_sh;
        for (int w = tid; w < Mr*NR; w += 128) {
            int j = w >> 4;        // NR == 16
            int r = w & 15;
            float dd = rd[j] - shfR_s[r];
            float v  = 0.25f * __expf(-etaR * dd * dd) * rf[j];
            atomicAdd(&accR[rs[j]*NR + r], v);
        }
    } else {
        // ========== ANGULAR (warps 4-7): warp-per-pair, lane = (a,z) ==========
        const int   wu     = wid - 4;           // 0..3
        const int   M      = cntA;
        const int   npair2 = M*(M-1)/2;
        const float etaA   = etaA_sh;
        const float zeta   = zeta_sh;
        const float twoM1  = (float)(2*M - 1);

        const int   a    = lane >> 3;           // 0..3
        const int   z    = lane & 7;            // 0..7
        const float cz   = czZ[z], sz = szZ[z];
        const float shfa = shfA_s[a];

        for (int u = wu; u < npair2; u += 4) {
            // closed-form decode of (p,q) with O(1) fixup (uniform across warp)
            float disc = twoM1*twoM1 - 8.0f*(float)u;
            int p = (int)floorf((twoM1 - __fsqrt_rn(disc)) * 0.5f);
            if ((p+1)*(2*M - p - 2) / 2 <= u) p++;
            if (p*(2*M - p - 1) / 2 > u) p--;
            int q = u - p*(2*M - p - 1)/2 + p + 1;

            // shared geometry (redundant per lane: free in warp-instructions)
            float dp = ad[p], dq = ad[q];
            float dot = adx[p]*adx[q] + ady[p]*ady[q] + adz[p]*adz[q];
            float dd  = fmaxf(dp*dq, 1e-8f);
            float cosA = 0.95f * __fdividef(dot, dd);
            float sinA = sqrtf(fmaxf(1.0f - cosA*cosA, 0.0f));
            float dsum = 0.5f * (dp + dq);
            float w2   = 2.0f * afc[p] * afc[q];

            int s1 = spA[p], s2 = spA[q];
            int lo = min(s1, s2), hi = max(s1, s2);
            int pidx = lo*SS - (lo*(lo-1))/2 + (hi - lo);

            // per-lane feature value
            float t  = dsum - shfa;
            float f2 = w2 * __expf(-etaA * t * t);
            float x  = 0.5f * (1.0f + cosA*cz + sinA*sz);
            float f1;
            if (zeta == 32.0f) {
                float x2 = x*x, x4 = x2*x2, x8 = x4*x4, x16 = x8*x8;
                f1 = x16*x16;
            } else {
                f1 = __powf(x, zeta);
            }
            // lane-consecutive -> bank-conflict-free; cross-warp collision deg <= 4
            atomicAdd(&accA[pidx*32 + lane], f1 * f2);
        }
    }
    __syncthreads();

    // ---- Write out: [radial (64) | angular (320)] contiguous per atom ----
    float* o = out + (size_t)aidx * OUTD;
    if (tid < RADD) o[tid] = accR[tid];
    for (int t = tid; t < ANGD; t += 256) o[RADD + t] = accA[t];
}

extern "C" void kernel_launch(void* const* d_in, const int* in_sizes, int n_in,
                              void* d_out, int out_size)
{
    const int*   species = (const int*)  d_in[0];
    const float* coords  = (const float*)d_in[1];
    const float* EtaR    = (const float*)d_in[2];
    const float* ShfR    = (const float*)d_in[3];
    const float* EtaA    = (const float*)d_in[4];
    const float* Zeta    = (const float*)d_in[5];
    const float* ShfA    = (const float*)d_in[6];
    const float* ShfZ    = (const float*)d_in[7];
    float* out = (float*)d_out;

    int B = in_sizes[0] / AA;   // species is [B, A]
    aev_kernel<<<B * AA, 256>>>(species, coords, EtaR, ShfR, EtaA, Zeta,
                                ShfA, ShfZ, out);
}

// round 8
// speedup vs baseline: 1.3626x; 1.3626x over previous
#include <cuda_runtime.h>
#include <math.h>

// Problem constants (fixed by the bench problem)
#define AA     48          // atoms per batch
#define SS     4           // num species
#define NR     16          // num radial shifts
#define NAA    4           // num angular radial shifts
#define NZ     8           // num angular shifts
#define NPAIRS (SS*(SS+1)/2)   // 10
#define RADD   (SS*NR)         // 64
#define ANGD   (NPAIRS*NAA*NZ) // 320
#define OUTD   (RADD+ANGD)     // 384
#define RCR    5.2f
#define RCA    3.5f
#define PI_F   3.14159265358979323846f
#define CHUNK  512             // pair-staging capacity per sweep

__global__ __launch_bounds__(256) void aev_kernel(
    const int*   __restrict__ species,   // [B, A]
    const float* __restrict__ coords,    // [B, A, 3]
    const float* __restrict__ EtaR,      // [1]
    const float* __restrict__ ShfR,      // [NR]
    const float* __restrict__ EtaA,      // [1]
    const float* __restrict__ Zeta,      // [1]
    const float* __restrict__ ShfA,      // [NAA]
    const float* __restrict__ ShfZ,      // [NZ]
    float*       __restrict__ out)       // [B, A, OUTD]
{
    // compacted neighbor lists
    __shared__ float rd[AA], rf[AA];
    __shared__ int   rs[AA];
    __shared__ float adx[AA], ady[AA], adz[AA], ad[AA], afc[AA];
    __shared__ int   spA[AA];
    __shared__ int   cntR, cntA;
    // per-pair staging (phase A output)
    __shared__ float pcos[CHUNK], psin[CHUNK], pdsum[CHUNK], pw2[CHUNK];
    __shared__ int   ppidx[CHUNK];

    const int tid  = threadIdx.x;
    const int wid  = tid >> 5;
    const int lane = tid & 31;
    const int aidx = blockIdx.x;
    const int i    = aidx % AA;
    const int b    = aidx / AA;

    // ---- prologue: params -> registers (latency hidden behind sync #1) ----
    const float etaR = EtaR[0];
    const float etaA = EtaA[0];
    const float zeta = Zeta[0];
    // radial feature params (tid < 64: s = tid>>4, r = tid&15)
    const float shfr = ShfR[tid & 15];
    // angular feature params (lane = a*8+z)
    const int   la   = lane >> 3;
    const float shfa = ShfA[la];
    {   }
    const float shz  = ShfZ[lane & 7];
    const float cz   = __cosf(shz);
    const float sz   = __sinf(shz);

    if (tid == 255) { cntR = 0; cntA = 0; }

    // distances in registers (threads 0..47), direct gmem loads
    float dxr=0, dyr=0, dzr=0, dr=0;
    bool  pvR=false, pvA=false;
    int   spj=0;
    if (tid < AA) {
        int j = tid;
        const float* cb = coords + (size_t)b*AA*3;
        float xi = cb[3*i], yi = cb[3*i+1], zi = cb[3*i+2];
        float dx = xi - cb[3*j], dy = yi - cb[3*j+1], dz = zi - cb[3*j+2];
        float d  = sqrtf(dx*dx + dy*dy + dz*dz);
        spj = species[b*AA + j];
        int spi = species[b*AA + i];
        bool pv = (spi >= 0) && (spj >= 0) && (j != i);
        dxr = dx; dyr = dy; dzr = dz; dr = d;
        pvR = pv && (d <= RCR);
        pvA = pv && (d <= RCA);
    }
    __syncthreads();   // #1: counters zeroed, params (regs) irrelevant

    // ---- compaction (threads 0..47) ----
    if (tid < AA) {
        if (pvR) {
            int s = atomicAdd(&cntR, 1);
            rd[s] = dr;
            rf[s] = 0.5f*__cosf(PI_F * dr * (1.0f/RCR)) + 0.5f;
            rs[s] = spj;
        }
        if (pvA) {
            int s = atomicAdd(&cntA, 1);
            adx[s] = dxr; ady[s] = dyr; adz[s] = dzr; ad[s] = dr;
            afc[s] = 0.5f*__cosf(PI_F * dr * (1.0f/RCA)) + 0.5f;
            spA[s] = spj;
        }
    }
    __syncthreads();   // #2

    const int M      = cntA;
    const int Mr     = cntR;
    const int npair2 = M*(M-1)/2;
    const float twoM1 = (float)(2*M - 1);
    float* o = out + (size_t)aidx * OUTD;

    // ---- radial: warps 0-1, register accumulation, immediate STG ----
    if (tid < RADD) {
        const int s = tid >> 4;
        float acc = 0.0f;
        for (int k = 0; k < Mr; k++) {
            float dd = rd[k] - shfr;
            float v  = 0.25f * __expf(-etaR * dd * dd) * rf[k];
            if (rs[k] == s) acc += v;
        }
        o[tid] = acc;
    }

    // ---- angular: chunked [phase A stage | warp-scan accumulate] ----
    // warp w accumulates pidx w (acc0) and, for w<2, pidx 8+w (acc1)
    const int pidxA = wid;
    const int pidxB = (wid < 2) ? (8 + wid) : -1;
    float acc0 = 0.0f, acc1 = 0.0f;

    for (int u0 = 0; u0 == 0 || u0 < npair2; u0 += CHUNK) {
        const int chunkN = min(CHUNK, npair2 - u0);

        // phase A on warps 2-7 (192 threads): geometry only, no exps
        if (tid >= 64) {
            for (int k = tid - 64; k < chunkN; k += 192) {
                int u = u0 + k;
                float disc = twoM1*twoM1 - 8.0f*(float)u;
                int p = (int)floorf((twoM1 - __fsqrt_rn(disc)) * 0.5f);
                if ((p+1)*(2*M - p - 2) / 2 <= u) p++;
                if (p*(2*M - p - 1) / 2 > u) p--;
                int q = u - p*(2*M - p - 1)/2 + p + 1;

                float dp = ad[p], dq = ad[q];
                float dot = adx[p]*adx[q] + ady[p]*ady[q] + adz[p]*adz[q];
                float dd  = fmaxf(dp*dq, 1e-8f);
                float cosA = 0.95f * __fdividef(dot, dd);
                float sinA = sqrtf(fmaxf(1.0f - cosA*cosA, 0.0f));

                int s1 = spA[p], s2 = spA[q];
                int lo = min(s1, s2), hi = max(s1, s2);

                pcos[k]  = cosA;
                psin[k]  = sinA;
                pdsum[k] = 0.5f * (dp + dq);
                pw2[k]   = 2.0f * afc[p] * afc[q];
                ppidx[k] = lo*SS - (lo*(lo-1))/2 + (hi - lo);
            }
        }
        __syncthreads();   // #3 (staging ready)

        // warp-scan: uniform pidx branch per pair, register accumulate
        for (int k = 0; k < chunkN; k++) {
            int pp = ppidx[k];
            bool m0 = (pp == pidxA);
            bool m1 = (pp == pidxB);
            if (m0 | m1) {
                float cosA = pcos[k], sinA = psin[k];
                float t  = pdsum[k] - shfa;
                float f2 = pw2[k] * __expf(-etaA * t * t);
                float x  = 0.5f * (1.0f + cosA*cz + sinA*sz);
                float f1;
                if (zeta == 32.0f) {
                    float x2 = x*x, x4 = x2*x2, x8 = x4*x4, x16 = x8*x8;
                    f1 = x16*x16;
                } else {
                    f1 = __powf(x, zeta);
                }
                float v = f1 * f2;
                if (m0) acc0 += v; else acc1 += v;
            }
        }
        __syncthreads();   // #4 (staging reusable)
    }

    // ---- angular writeout: one coalesced 128B STG per warp ----
    o[RADD + pidxA*32 + lane] = acc0;
    if (pidxB >= 0) o[RADD + pidxB*32 + lane] = acc1;
}

extern "C" void kernel_launch(void* const* d_in, const int* in_sizes, int n_in,
                              void* d_out, int out_size)
{
    const int*   species = (const int*)  d_in[0];
    const float* coords  = (const float*)d_in[1];
    const float* EtaR    = (const float*)d_in[2];
    const float* ShfR    = (const float*)d_in[3];
    const float* EtaA    = (const float*)d_in[4];
    const float* Zeta    = (const float*)d_in[5];
    const float* ShfA    = (const float*)d_in[6];
    const float* ShfZ    = (const float*)d_in[7];
    float* out = (float*)d_out;

    int B = in_sizes[0] / AA;   // species is [B, A]
    aev_kernel<<<B * AA, 256>>>(species, coords, EtaR, ShfR, EtaA, Zeta,
                                ShfA, ShfZ, out);
}

// round 10
// speedup vs baseline: 1.4036x; 1.0301x over previous
#include <cuda_runtime.h>
#include <math.h>

// Problem constants (fixed by the bench problem)
#define AA     48          // atoms per batch
#define SS     4           // num species
#define NR     16          // num radial shifts
#define NAA    4           // num angular radial shifts
#define NZ     8           // num angular shifts
#define NPAIRS (SS*(SS+1)/2)   // 10
#define RADD   (SS*NR)         // 64
#define ANGD   (NPAIRS*NAA*NZ) // 320
#define OUTD   (RADD+ANGD)     // 384
#define RCR    5.2f
#define RCA    3.5f
#define PI_F   3.14159265358979323846f
#define CHUNK  512             // pair-staging capacity per sweep (mult of 4)

__global__ __launch_bounds__(384) void aev_kernel(
    const int*   __restrict__ species,   // [B, A]
    const float* __restrict__ coords,    // [B, A, 3]
    const float* __restrict__ EtaR,      // [1]
    const float* __restrict__ ShfR,      // [NR]
    const float* __restrict__ EtaA,      // [1]
    const float* __restrict__ Zeta,      // [1]
    const float* __restrict__ ShfA,      // [NAA]
    const float* __restrict__ ShfZ,      // [NZ]
    float*       __restrict__ out)       // [B, A, OUTD]
{
    // compacted neighbor lists
    __shared__ float rd[AA], rf[AA];
    __shared__ int   rs[AA];
    __shared__ float adx[AA], ady[AA], adz[AA], ad[AA], afc[AA];
    __shared__ int   spA[AA];
    __shared__ int   cntR, cntA;
    // per-pair staging (phase A output); ppidx 16B-aligned for int4 loads
    __shared__ float pcos[CHUNK], psin[CHUNK], pdsum[CHUNK], pw2[CHUNK];
    __shared__ __align__(16) int ppidx[CHUNK + 4];

    const int tid  = threadIdx.x;
    const int wid  = tid >> 5;
    const int lane = tid & 31;
    const int aidx = blockIdx.x;
    const int i    = aidx % AA;
    const int b    = aidx / AA;

    // ---- prologue: params -> registers ----
    const float etaR = EtaR[0];
    const float etaA = EtaA[0];
    const float zeta = Zeta[0];
    const float shfr = ShfR[tid & 15];           // radial feature param
    const float shfa = ShfA[lane >> 3];          // angular feature params
    const float shz  = ShfZ[lane & 7];
    const float cz   = __cosf(shz);
    const float sz   = __sinf(shz);

    if (tid == 383) { cntR = 0; cntA = 0; }

    // distances in registers (threads 0..47)
    float dxr=0, dyr=0, dzr=0, drr=0;
    bool  pvR=false, pvA=false;
    int   spj=0;
    if (tid < AA) {
        int j = tid;
        const float* cb = coords + (size_t)b*AA*3;
        float xi = cb[3*i], yi = cb[3*i+1], zi = cb[3*i+2];
        float dx = xi - cb[3*j], dy = yi - cb[3*j+1], dz = zi - cb[3*j+2];
        float d  = sqrtf(dx*dx + dy*dy + dz*dz);
        spj = species[b*AA + j];
        int spi = species[b*AA + i];
        bool pv = (spi >= 0) && (spj >= 0) && (j != i);
        dxr = dx; dyr = dy; dzr = dz; drr = d;
        pvR = pv && (d <= RCR);
        pvA = pv && (d <= RCA);
    }
    __syncthreads();   // #1: counters zeroed

    if (tid < AA) {
        if (pvR) {
            int s = atomicAdd(&cntR, 1);
            rd[s] = drr;
            rf[s] = 0.5f*__cosf(PI_F * drr * (1.0f/RCR)) + 0.5f;
            rs[s] = spj;
        }
        if (pvA) {
            int s = atomicAdd(&cntA, 1);
            adx[s] = dxr; ady[s] = dyr; adz[s] = dzr; ad[s] = drr;
            afc[s] = 0.5f*__cosf(PI_F * drr * (1.0f/RCA)) + 0.5f;
            spA[s] = spj;
        }
    }
    __syncthreads();   // #2

    const int M      = cntA;
    const int Mr     = cntR;
    const int npair2 = M*(M-1)/2;
    const float twoM1 = (float)(2*M - 1);
    float* o = out + (size_t)aidx * OUTD;

    // warps 0..9: one pidx class each; warps 10..11: radial
    const int pidxW = wid;              // valid for wid < 10
    float acc = 0.0f;

    for (int u0 = 0; u0 == 0 || u0 < npair2; u0 += CHUNK) {
        const int chunkN = min(CHUNK, npair2 - u0);
        const int chunkN4 = (chunkN + 3) & ~3;

        // phase A on all 384 threads: geometry only
        for (int k = tid; k < chunkN4; k += 384) {
            int u = u0 + k;
            int pp = -1;
            if (k < chunkN) {
                float disc = fmaxf(twoM1*twoM1 - 8.0f*(float)u, 0.0f);
                int p = (int)floorf((twoM1 - __fsqrt_rn(disc)) * 0.5f);
                if (p > M-2) p = M-2;
                if ((p+1)*(2*M - p - 2) / 2 <= u) p++;
                if (p*(2*M - p - 1) / 2 > u) p--;
                int q = u - p*(2*M - p - 1)/2 + p + 1;

                float dp = ad[p], dq = ad[q];
                float dot = adx[p]*adx[q] + ady[p]*ady[q] + adz[p]*adz[q];
                float dd  = fmaxf(dp*dq, 1e-8f);
                float cosA = 0.95f * __fdividef(dot, dd);
                float sinA = sqrtf(fmaxf(1.0f - cosA*cosA, 0.0f));

                int s1 = spA[p], s2 = spA[q];
                int lo = min(s1, s2), hi = max(s1, s2);

                pcos[k]  = cosA;
                psin[k]  = sinA;
                pdsum[k] = 0.5f * (dp + dq);
                pw2[k]   = 2.0f * afc[p] * afc[q];
                pp = lo*SS - (lo*(lo-1))/2 + (hi - lo);
            }
            ppidx[k] = pp;
        }
        __syncthreads();   // #3 (staging ready)

        if (wid < 10) {
            // ---- angular scan: int4 over ppidx, process matches ----
            for (int k4 = 0; k4 < chunkN4; k4 += 4) {
                int4 pp = *(const int4*)&ppidx[k4];
                #pragma unroll
                for (int e = 0; e < 4; e++) {
                    int ppe = (e==0) ? pp.x : (e==1) ? pp.y : (e==2) ? pp.z : pp.w;
                    if (ppe == pidxW) {
                        int k = k4 + e;
                        float cosA = pcos[k], sinA = psin[k];
                        float t  = pdsum[k] - shfa;
                        float f2 = pw2[k] * __expf(-etaA * t * t);
                        float x  = 0.5f * (1.0f + cosA*cz + sinA*sz);
                        float f1;
                        if (zeta == 32.0f) {
                            float x2 = x*x, x4 = x2*x2, x8 = x4*x4, x16 = x8*x8;
                            f1 = x16*x16;
                        } else {
                            f1 = __powf(x, zeta);
                        }
                        acc += f1 * f2;
                    }
                }
            }
        } else if (u0 == 0) {
            // ---- radial (warps 10-11, concurrent with the scan) ----
            const int tr = tid - 320;        // 0..63
            const int s  = tr >> 4;
            float ra = 0.0f;
            for (int k = 0; k < Mr; k++) {
                float dd = rd[k] - shfr;
                float v  = 0.25f * __expf(-etaR * dd * dd) * rf[k];
                if (rs[k] == s) ra += v;
            }
            o[tr] = ra;
        }
        __syncthreads();   // #4 (staging reusable)
    }

    // ---- angular writeout: one coalesced 128B STG per warp ----
    if (wid < 10) o[RADD + pidxW*32 + lane] = acc;
}

extern "C" void kernel_launch(void* const* d_in, const int* in_sizes, int n_in,
                              void* d_out, int out_size)
{
    const int*   species = (const int*)  d_in[0];
    const float* coords  = (const float*)d_in[1];
    const float* EtaR    = (const float*)d_in[2];
    const float* ShfR    = (const float*)d_in[3];
    const float* EtaA    = (const float*)d_in[4];
    const float* Zeta    = (const float*)d_in[5];
    const float* ShfA    = (const float*)d_in[6];
    const float* ShfZ    = (const float*)d_in[7];
    float* out = (float*)d_out;

    int B = in_sizes[0] / AA;   // species is [B, A]
    aev_kernel<<<B * AA, 384>>>(species, coords, EtaR, ShfR, EtaA, Zeta,
                                ShfA, ShfZ, out);
}

// round 12
// speedup vs baseline: 1.5032x; 1.0710x over previous
#include <cuda_runtime.h>
#include <math.h>

// Problem constants (fixed by the bench problem)
#define AA     48          // atoms per batch
#define SS     4           // num species
#define NR     16          // num radial shifts
#define NAA    4           // num angular radial shifts
#define NZ     8           // num angular shifts
#define NPAIRS (SS*(SS+1)/2)   // 10
#define RADD   (SS*NR)         // 64
#define ANGD   (NPAIRS*NAA*NZ) // 320
#define OUTD   (RADD+ANGD)     // 384
#define RCR    5.2f
#define RCA    3.5f
#define PI_F   3.14159265358979323846f

__global__ __launch_bounds__(384) void aev_kernel(
    const int*   __restrict__ species,   // [B, A]
    const float* __restrict__ coords,    // [B, A, 3]
    const float* __restrict__ EtaR,      // [1]
    const float* __restrict__ ShfR,      // [NR]
    const float* __restrict__ EtaA,      // [1]
    const float* __restrict__ Zeta,      // [1]
    const float* __restrict__ ShfA,      // [NAA]
    const float* __restrict__ ShfZ,      // [NZ]
    float*       __restrict__ out)       // [B, A, OUTD]
{
    // species-bucketed neighbor lists (bucket s at base s*AA)
    __shared__ float4 abuc[SS*AA];      // angular: dx,dy,dz,d
    __shared__ float  afcb[SS*AA];      // angular: fc
    __shared__ float2 rbuc[SS*AA];      // radial:  d, fc
    __shared__ int    cntA[SS], cntR[SS];

    const int tid  = threadIdx.x;
    const int wid  = tid >> 5;
    const int lane = tid & 31;
    const int aidx = blockIdx.x;
    const int i    = aidx % AA;
    const int b    = aidx / AA;

    // ---- params -> registers (independent LDGs, overlap prologue) ----
    const float etaR = EtaR[0];
    const float etaA = EtaA[0];
    const float zeta = Zeta[0];
    const float shfr = ShfR[tid & 15];          // radial feature (s=tr>>4, r=tid&15)
    const float shfa = ShfA[lane >> 3];         // angular feature (a,z)
    const float shz  = ShfZ[lane & 7];
    const float cz   = __cosf(shz);
    const float sz   = __sinf(shz);

    // counters zeroed by threads outside the 0..47 distance group
    if (tid >= 64 && tid < 64 + SS) cntA[tid - 64] = 0;
    if (tid >= 96 && tid < 96 + SS) cntR[tid - 96] = 0;

    // ---- distances in registers (threads 0..47) ----
    float dxr=0, dyr=0, dzr=0, drr=0, fcrv=0, fcav=0;
    bool  pvR=false, pvA=false;
    int   spj=0;
    if (tid < AA) {
        int j = tid;
        const float* cb = coords + (size_t)b*AA*3;
        float xi = cb[3*i], yi = cb[3*i+1], zi = cb[3*i+2];
        float dx = xi - cb[3*j], dy = yi - cb[3*j+1], dz = zi - cb[3*j+2];
        float d  = sqrtf(dx*dx + dy*dy + dz*dz);
        spj = species[b*AA + j];
        int spi = species[b*AA + i];
        bool pv = (spi >= 0) && (spj >= 0) && (j != i);
        dxr = dx; dyr = dy; dzr = dz; drr = d;
        pvR = pv && (d <= RCR);
        pvA = pv && (d <= RCA);
        fcrv = 0.5f*__cosf(PI_F * d * (1.0f/RCR)) + 0.5f;
        fcav = 0.5f*__cosf(PI_F * d * (1.0f/RCA)) + 0.5f;
    }
    __syncthreads();   // #1: counters ready

    // ---- bucketed compaction ----
    if (tid < AA) {
        if (pvR) {
            int s = atomicAdd(&cntR[spj], 1);
            rbuc[spj*AA + s] = make_float2(drr, fcrv);
        }
        if (pvA) {
            int s = atomicAdd(&cntA[spj], 1);
            abuc[spj*AA + s] = make_float4(dxr, dyr, dzr, drr);
            afcb[spj*AA + s] = fcav;
        }
    }
    __syncthreads();   // #2: buckets ready

    float* o = out + (size_t)aidx * OUTD;

    if (wid < NPAIRS) {
        // ===== ANGULAR: warp = pair-class (lo,hi), lane = (a,z) feature =====
        const int lo    = (wid < 4) ? 0 : (wid < 7) ? 1 : (wid < 9) ? 2 : 3;
        const int basew = (wid < 4) ? 0 : (wid < 7) ? 4 : (wid < 9) ? 7 : 9;
        const int hi    = lo + (wid - basew);
        const int nLo = cntA[lo], nHi = cntA[hi];
        const int bLo = lo*AA, bHi = hi*AA;
        float acc = 0.0f;

        if (lo == hi) {
            for (int p = 0; p < nLo - 1; p++) {
                float4 P  = abuc[bLo + p];
                float fcp = afcb[bLo + p];
                for (int q = p + 1; q < nLo; q++) {
                    float4 Q  = abuc[bLo + q];
                    float fcq = afcb[bLo + q];
                    float dot = P.x*Q.x + P.y*Q.y + P.z*Q.z;
                    float dd  = fmaxf(P.w*Q.w, 1e-8f);
                    float cosA = 0.95f * __fdividef(dot, dd);
                    float sinA = sqrtf(fmaxf(1.0f - cosA*cosA, 0.0f));
                    float t  = 0.5f*(P.w + Q.w) - shfa;
                    float f2 = 2.0f * fcp * fcq * __expf(-etaA * t * t);
                    float x  = 0.5f + 0.5f*(cosA*cz + sinA*sz);
                    float f1;
                    if (zeta == 32.0f) {
                        float x2 = x*x, x4 = x2*x2, x8 = x4*x4, x16 = x8*x8;
                        f1 = x16*x16;
                    } else {
                        f1 = __powf(x, zeta);
                    }
                    acc += f1 * f2;
                }
            }
        } else {
            for (int p = 0; p < nLo; p++) {
                float4 P  = abuc[bLo + p];
                float fcp = afcb[bLo + p];
                for (int q = 0; q < nHi; q++) {
                    float4 Q  = abuc[bHi + q];
                    float fcq = afcb[bHi + q];
                    float dot = P.x*Q.x + P.y*Q.y + P.z*Q.z;
                    float dd  = fmaxf(P.w*Q.w, 1e-8f);
                    float cosA = 0.95f * __fdividef(dot, dd);
                    float sinA = sqrtf(fmaxf(1.0f - cosA*cosA, 0.0f));
                    float t  = 0.5f*(P.w + Q.w) - shfa;
                    float f2 = 2.0f * fcp * fcq * __expf(-etaA * t * t);
                    float x  = 0.5f + 0.5f*(cosA*cz + sinA*sz);
                    float f1;
                    if (zeta == 32.0f) {
                        float x2 = x*x, x4 = x2*x2, x8 = x4*x4, x16 = x8*x8;
                        f1 = x16*x16;
                    } else {
                        f1 = __powf(x, zeta);
                    }
                    acc += f1 * f2;
                }
            }
        }
        o[RADD + wid*32 + lane] = acc;
    } else {
        // ===== RADIAL: thread = (s,r) feature, loops over bucket s only =====
        const int tr = tid - NPAIRS*32;     // 0..63
        const int s  = tr >> 4;
        const int n  = cntR[s];
        const int bs = s*AA;
        float ra = 0.0f;
        for (int k = 0; k < n; k++) {
            float2 v  = rbuc[bs + k];
            float  dd = v.x - shfr;
            ra += __expf(-etaR * dd * dd) * v.y;
        }
        o[tr] = 0.25f * ra;
    }
}

extern "C" void kernel_launch(void* const* d_in, const int* in_sizes, int n_in,
                              void* d_out, int out_size)
{
    const int*   species = (const int*)  d_in[0];
    const float* coords  = (const float*)d_in[1];
    const float* EtaR    = (const float*)d_in[2];
    const float* ShfR    = (const float*)d_in[3];
    const float* EtaA    = (const float*)d_in[4];
    const float* Zeta    = (const float*)d_in[5];
    const float* ShfA    = (const float*)d_in[6];
    const float* ShfZ    = (const float*)d_in[7];
    float* out = (float*)d_out;

    int B = in_sizes[0] / AA;   // species is [B, A]
    aev_kernel<<<B * AA, 384>>>(species, coords, EtaR, ShfR, EtaA, Zeta,
                                ShfA, ShfZ, out);
}